// round 1
// baseline (speedup 1.0000x reference)
#include <cuda_runtime.h>
#include <cstdint>
#include <cstddef>

// Problem constants
#define NB   8192
#define NA   56
#define NE   128
#define NH2  8     // 2*H
#define NHD  16
#define XS_W 136   // conv1 smem row width (128 + 6 halo + pad)

// ---------------- scratch (device globals; no allocation allowed) ----------
__device__ float g_wemb_t[56 * 7 * 56];       // [a_in][k][a_out]
__device__ float g_watlas_t[128 * 7 * 128];   // [e_in][k][e_out]
__device__ float g_wk_t[128 * 128];           // [e][o]
__device__ float g_h1[(size_t)NB * 128 * 64]; // [b][e][64] : a at +3, halo zeros
__device__ float g_q[NB * 128];               // q pre-LN

// ---------------- f32x2 helpers --------------------------------------------
__device__ __forceinline__ void fma2(unsigned long long &d,
                                     unsigned long long a,
                                     unsigned long long b) {
    asm("fma.rn.f32x2 %0, %1, %2, %3;" : "=l"(d) : "l"(a), "l"(b), "l"(d));
}
__device__ __forceinline__ unsigned long long bc2(float x) {
    unsigned int xi = __float_as_uint(x);
    unsigned long long r;
    asm("mov.b64 %0, {%1, %2};" : "=l"(r) : "r"(xi), "r"(xi));
    return r;
}
__device__ __forceinline__ float2 unpk(unsigned long long v) {
    unsigned int lo, hi;
    asm("mov.b64 {%0, %1}, %2;" : "=r"(lo), "=r"(hi) : "l"(v));
    float2 f; f.x = __uint_as_float(lo); f.y = __uint_as_float(hi);
    return f;
}
__device__ __forceinline__ float silu_f(float v) {
    return v / (1.0f + __expf(-v));
}

// ---------------- K0: repack weights ---------------------------------------
__global__ void repack_kernel(const float* __restrict__ w_emb,
                              const float* __restrict__ w_atlas,
                              const float* __restrict__ w_k) {
    int i = blockIdx.x * 256 + threadIdx.x;
    if (i < 56 * 56 * 7) {
        int ao = i / 392, r = i % 392, ai = r / 7, k = r % 7;
        g_wemb_t[(ai * 7 + k) * 56 + ao] = w_emb[i];
    }
    if (i < 128 * 128 * 7) {
        int eo = i / 896, r = i % 896, ei = r / 7, k = r % 7;
        g_watlas_t[(ei * 7 + k) * 128 + eo] = w_atlas[i];
    }
    if (i < 128 * 128) {
        int o = i / 128, e = i % 128;
        g_wk_t[e * 128 + o] = w_k[i];
    }
}

// ---------------- K1: conv1 (over E axis) + SiLU -> h1T --------------------
// 4 batches per CTA of 256 threads. Thread: 64-lane group per batch,
// covers e0=2t, e0+1; f32x2 lanes = a_out pairs (all 56 a_out).
__global__ void __launch_bounds__(256, 1)
conv1_kernel(const float* __restrict__ x, const float* __restrict__ b_emb) {
    extern __shared__ float smem1[];
    int tid = threadIdx.x;
    int sub = tid >> 6;
    int t   = tid & 63;
    int b   = blockIdx.x * 4 + sub;
    float* xs = smem1 + sub * 56 * XS_W;

    const float* xb = x + (size_t)b * 56 * 128;
    for (int i = t; i < 56 * 128; i += 64) {
        int a = i >> 7, e = i & 127;
        xs[a * XS_W + 3 + e] = xb[i];
    }
    if (t < 56) {
        float* row = xs + t * XS_W;
        row[0] = 0.f; row[1] = 0.f; row[2] = 0.f;
        row[131] = 0.f; row[132] = 0.f; row[133] = 0.f; row[134] = 0.f; row[135] = 0.f;
    }
    __syncthreads();

    int e0 = 2 * t;
    unsigned long long acc0[28], acc1[28];
#pragma unroll
    for (int j = 0; j < 28; j++) { acc0[j] = 0ULL; acc1[j] = 0ULL; }

    for (int ai = 0; ai < 56; ai++) {
        const float* xr = xs + ai * XS_W + e0;
        float xv[8];
#pragma unroll
        for (int j = 0; j < 8; j++) xv[j] = xr[j];
#pragma unroll
        for (int k = 0; k < 7; k++) {
            unsigned long long xb0 = bc2(xv[k]);
            unsigned long long xb1 = bc2(xv[k + 1]);
            const ulonglong2* wr =
                reinterpret_cast<const ulonglong2*>(g_wemb_t + (ai * 7 + k) * 56);
#pragma unroll
            for (int p = 0; p < 14; p++) {
                ulonglong2 w = wr[p];
                fma2(acc0[2 * p],     w.x, xb0);
                fma2(acc1[2 * p],     w.x, xb1);
                fma2(acc0[2 * p + 1], w.y, xb0);
                fma2(acc1[2 * p + 1], w.y, xb1);
            }
        }
    }

#pragma unroll
    for (int v = 0; v < 2; v++) {
        float* dst = g_h1 + ((size_t)b * 128 + e0 + v) * 64;
        dst[0] = 0.f; dst[1] = 0.f; dst[2] = 0.f;
        dst[59] = 0.f; dst[60] = 0.f; dst[61] = 0.f; dst[62] = 0.f; dst[63] = 0.f;
        const unsigned long long* av = v ? acc1 : acc0;
#pragma unroll
        for (int j = 0; j < 28; j++) {
            float2 f = unpk(av[j]);
            dst[3 + 2 * j] = silu_f(f.x + b_emb[2 * j]);
            dst[4 + 2 * j] = silu_f(f.y + b_emb[2 * j + 1]);
        }
    }
}

// ---------------- K2: conv2 (over A axis) + SiLU + mean -> q ---------------
// 1 batch per CTA of 224 threads: tx=a-pair (28), g=eo-group (8 groups of 16).
__global__ void __launch_bounds__(224)
conv2_kernel(const float* __restrict__ b_atlas) {
    __shared__ __align__(16) float h1s[128 * 64];
    __shared__ float qsum[128];
    int tid = threadIdx.x;
    int b = blockIdx.x;

    const float4* src = reinterpret_cast<const float4*>(g_h1 + (size_t)b * 8192);
    float4* dst4 = reinterpret_cast<float4*>(h1s);
    for (int i = tid; i < 2048; i += 224) dst4[i] = src[i];
    if (tid < 128) qsum[tid] = 0.f;
    __syncthreads();

    int tx = tid % 28, g = tid / 28;
    int a0 = 2 * tx, eo0 = g * 16;

    unsigned long long acc0[8], acc1[8];
#pragma unroll
    for (int j = 0; j < 8; j++) { acc0[j] = 0ULL; acc1[j] = 0ULL; }

    for (int ei = 0; ei < 128; ei++) {
        const float* hr = h1s + ei * 64 + a0;
        float xv[8];
#pragma unroll
        for (int j = 0; j < 8; j++) xv[j] = hr[j];
#pragma unroll
        for (int k = 0; k < 7; k++) {
            unsigned long long xb0 = bc2(xv[k]);
            unsigned long long xb1 = bc2(xv[k + 1]);
            const ulonglong2* wr = reinterpret_cast<const ulonglong2*>(
                g_watlas_t + (ei * 7 + k) * 128 + eo0);
#pragma unroll
            for (int p = 0; p < 4; p++) {
                ulonglong2 w = wr[p];
                fma2(acc0[2 * p],     w.x, xb0);
                fma2(acc1[2 * p],     w.x, xb1);
                fma2(acc0[2 * p + 1], w.y, xb0);
                fma2(acc1[2 * p + 1], w.y, xb1);
            }
        }
    }

    // silu + partial mean over this thread's two a positions
    float s[16];
#pragma unroll
    for (int j = 0; j < 8; j++) {
        float2 fa = unpk(acc0[j]);   // eo0+2j, eo0+2j+1 @ a0
        float2 fb = unpk(acc1[j]);   // @ a0+1
        float ba = b_atlas[eo0 + 2 * j];
        float bb = b_atlas[eo0 + 2 * j + 1];
        s[2 * j]     = silu_f(fa.x + ba) + silu_f(fb.x + ba);
        s[2 * j + 1] = silu_f(fa.y + bb) + silu_f(fb.y + bb);
    }
#pragma unroll
    for (int j = 0; j < 16; j++) atomicAdd(&qsum[eo0 + j], s[j]);
    __syncthreads();
    if (tid < 128) g_q[b * 128 + tid] = qsum[tid] * (1.0f / 56.0f);
}

// ---------------- K3: k-proj + LN + attention + diff-softmax ---------------
// 2 batches per CTA of 128 threads; half = tid>>6, t = tid&63.
__global__ void __launch_bounds__(128, 1)
attn_kernel(const float* __restrict__ x,
            const float* __restrict__ qn_w, const float* __restrict__ qn_b,
            const float* __restrict__ kn_w, const float* __restrict__ kn_b,
            const float* __restrict__ lq1, const float* __restrict__ lk1,
            const float* __restrict__ lq2, const float* __restrict__ lk2,
            float* __restrict__ out) {
    extern __shared__ float sm[];
    int tid = threadIdx.x;
    int half = tid >> 6, t = tid & 63;
    int b = blockIdx.x * 2 + half;

    float* xsT = sm + half * 7168;                 // [e][l], l contiguous
    float* ks  = sm + 14336 + half * 7168;         // [l][o]
    float* qv  = sm + 28672 + half * 128;
    float* sc  = sm + 28928 + half * 448;          // [h2][l]
    float* dd  = sm + 29824 + half * 224;          // [hp][l]
    float* lam = sm + 30272 + half;

    // phase 1: load x transposed, q, lambda
    const float* xb = x + (size_t)b * 7168;
    for (int i = t; i < 7168; i += 64) {
        int l = i >> 7, e = i & 127;
        xsT[e * 56 + l] = xb[i];
    }
    for (int i = t; i < 128; i += 64) qv[i] = g_q[b * 128 + i];
    if (t == 0) {
        float s1 = 0.f, s2 = 0.f;
#pragma unroll
        for (int d = 0; d < 16; d++) { s1 += lq1[d] * lk1[d]; s2 += lq2[d] * lk2[d]; }
        lam[0] = __expf(s1) - __expf(s2) + 0.7f;
    }
    __syncthreads();

    // phase 2: k projection, o0 = t, o1 = t + 64; f32x2 lanes = l pairs
    unsigned long long acc0[28], acc1[28];
#pragma unroll
    for (int p = 0; p < 28; p++) { acc0[p] = 0ULL; acc1[p] = 0ULL; }
    for (int e = 0; e < 128; e++) {
        unsigned long long wb0 = bc2(g_wk_t[e * 128 + t]);
        unsigned long long wb1 = bc2(g_wk_t[e * 128 + t + 64]);
        const unsigned long long* xr =
            reinterpret_cast<const unsigned long long*>(xsT + e * 56);
#pragma unroll
        for (int p = 0; p < 28; p++) {
            unsigned long long xq = xr[p];
            fma2(acc0[p], xq, wb0);
            fma2(acc1[p], xq, wb1);
        }
    }
#pragma unroll
    for (int p = 0; p < 28; p++) {
        float2 f0 = unpk(acc0[p]);
        ks[(2 * p) * 128 + t]     = f0.x;
        ks[(2 * p + 1) * 128 + t] = f0.y;
        float2 f1 = unpk(acc1[p]);
        ks[(2 * p) * 128 + t + 64]     = f1.x;
        ks[(2 * p + 1) * 128 + t + 64] = f1.y;
    }
    __syncthreads();

    // phase 3: LayerNorm k (448 groups) and q (8 groups)
    for (int gI = t; gI < 448; gI += 64) {
        int l = gI >> 3, h = gI & 7;
        float* kp = ks + l * 128 + h * 16;
        float m = 0.f;
#pragma unroll
        for (int d = 0; d < 16; d++) m += kp[d];
        m *= (1.0f / 16.0f);
        float var = 0.f;
#pragma unroll
        for (int d = 0; d < 16; d++) { float dv = kp[d] - m; var += dv * dv; }
        var *= (1.0f / 16.0f);
        float rs = rsqrtf(var + 1e-5f);
#pragma unroll
        for (int d = 0; d < 16; d++)
            kp[d] = (kp[d] - m) * rs * kn_w[d] + kn_b[d];
    }
    if (t < 8) {
        float* qp = qv + t * 16;
        float m = 0.f;
#pragma unroll
        for (int d = 0; d < 16; d++) m += qp[d];
        m *= (1.0f / 16.0f);
        float var = 0.f;
#pragma unroll
        for (int d = 0; d < 16; d++) { float dv = qp[d] - m; var += dv * dv; }
        var *= (1.0f / 16.0f);
        float rs = rsqrtf(var + 1e-5f);
#pragma unroll
        for (int d = 0; d < 16; d++)
            qp[d] = ((qp[d] - m) * rs * qn_w[d] + qn_b[d]) * 0.25f; // * HD^-0.5
    }
    __syncthreads();

    // phase 4: attention scores
    for (int gI = t; gI < 448; gI += 64) {
        int l = gI >> 3, h = gI & 7;
        const float* kp = ks + l * 128 + h * 16;
        const float* qp = qv + h * 16;
        float s = 0.f;
#pragma unroll
        for (int d = 0; d < 16; d++) s += qp[d] * kp[d];
        sc[h * 56 + l] = s;
    }
    __syncthreads();

    // phase 5: softmax over l per head (8 rows)
    if (t < 8) {
        float* r = sc + t * 56;
        float mx = -1e30f;
        for (int l = 0; l < 56; l++) mx = fmaxf(mx, r[l]);
        float sum = 0.f;
        for (int l = 0; l < 56; l++) { float e = __expf(r[l] - mx); r[l] = e; sum += e; }
        float inv = 1.0f / sum;
        for (int l = 0; l < 56; l++) r[l] *= inv;
    }
    __syncthreads();

    // phase 6: diff + softmax per head pair (4 rows)
    if (t < 4) {
        float lamv = lam[0];
        const float* p0 = sc + (2 * t) * 56;
        const float* p1 = sc + (2 * t + 1) * 56;
        float* dr = dd + t * 56;
        float mx = -1e30f;
        for (int l = 0; l < 56; l++) {
            float d = p0[l] - lamv * p1[l];
            dr[l] = d;
            mx = fmaxf(mx, d);
        }
        float sum = 0.f;
        for (int l = 0; l < 56; l++) { float e = __expf(dr[l] - mx); dr[l] = e; sum += e; }
        float inv = 1.0f / sum;
        for (int l = 0; l < 56; l++) dr[l] *= inv;
    }
    __syncthreads();

    // phase 7: mean over 4 head pairs -> out[b][l]
    if (t < 56) {
        float o = 0.25f * (dd[t - half * 224 + half * 224] ); // placeholder avoided below
        o = 0.25f * (dd[t] + dd[56 + t] + dd[112 + t] + dd[168 + t]);
        out[(size_t)b * 56 + t] = o;
    }
}

// ---------------- launch ----------------------------------------------------
extern "C" void kernel_launch(void* const* d_in, const int* in_sizes, int n_in,
                              void* d_out, int out_size) {
    const float* x       = (const float*)d_in[0];
    const float* w_emb   = (const float*)d_in[1];
    const float* b_emb   = (const float*)d_in[2];
    const float* w_atlas = (const float*)d_in[3];
    const float* b_atlas = (const float*)d_in[4];
    const float* w_k     = (const float*)d_in[5];
    const float* qn_w    = (const float*)d_in[6];
    const float* qn_b    = (const float*)d_in[7];
    const float* kn_w    = (const float*)d_in[8];
    const float* kn_b    = (const float*)d_in[9];
    const float* lq1     = (const float*)d_in[10];
    const float* lk1     = (const float*)d_in[11];
    const float* lq2     = (const float*)d_in[12];
    const float* lk2     = (const float*)d_in[13];
    float* out = (float*)d_out;

    const int SMEM1 = 4 * 56 * XS_W * (int)sizeof(float);   // 121,856 B
    const int SMEM3 = 30274 * (int)sizeof(float);           // 121,096 B
    cudaFuncSetAttribute((const void*)conv1_kernel,
                         cudaFuncAttributeMaxDynamicSharedMemorySize, SMEM1);
    cudaFuncSetAttribute((const void*)attn_kernel,
                         cudaFuncAttributeMaxDynamicSharedMemorySize, SMEM3);

    repack_kernel<<<448, 256>>>(w_emb, w_atlas, w_k);
    conv1_kernel<<<NB / 4, 256, SMEM1>>>(x, b_emb);
    conv2_kernel<<<NB, 224>>>(b_atlas);
    attn_kernel<<<NB / 2, 128, SMEM3>>>(x, qn_w, qn_b, kn_w, kn_b,
                                        lq1, lk1, lq2, lk2, out);
    (void)in_sizes; (void)n_in; (void)out_size;
}

// round 3
// speedup vs baseline: 1.4634x; 1.4634x over previous
#include <cuda_runtime.h>
#include <cstdint>
#include <cstddef>

#define NB   8192
#define XS_W 136   // conv1 smem row width (halo 3+5, padded)

// ---------------- scratch (device globals) ----------------------------------
__device__ __align__(16) float g_wemb_t[56 * 7 * 56];       // [a_in][k][a_out]
__device__ __align__(16) float g_watlas_t[128 * 7 * 128];   // [e_in][k][e_out]
__device__ __align__(16) float g_wk_t[128 * 128];           // [e][o]
__device__ __align__(16) float g_h1[(size_t)NB * 128 * 64]; // [b][e][a+3], halo 0
__device__ __align__(16) float g_q[NB * 128];               // q pre-LN

// ---------------- f32x2 helpers ---------------------------------------------
__device__ __forceinline__ void fma2(unsigned long long &d,
                                     unsigned long long a,
                                     unsigned long long b) {
    asm("fma.rn.f32x2 %0, %1, %2, %3;" : "=l"(d) : "l"(a), "l"(b), "l"(d));
}
__device__ __forceinline__ unsigned long long bc2(float x) {
    unsigned int xi = __float_as_uint(x);
    unsigned long long r;
    asm("mov.b64 %0, {%1, %2};" : "=l"(r) : "r"(xi), "r"(xi));
    return r;
}
__device__ __forceinline__ float2 unpk(unsigned long long v) {
    unsigned int lo, hi;
    asm("mov.b64 {%0, %1}, %2;" : "=r"(lo), "=r"(hi) : "l"(v));
    float2 f; f.x = __uint_as_float(lo); f.y = __uint_as_float(hi);
    return f;
}
__device__ __forceinline__ float silu_f(float v) {
    return v / (1.0f + __expf(-v));
}

// ---------------- K0: repack weights ----------------------------------------
__global__ void repack_kernel(const float* __restrict__ w_emb,
                              const float* __restrict__ w_atlas,
                              const float* __restrict__ w_k) {
    int i = blockIdx.x * 256 + threadIdx.x;
    if (i < 56 * 56 * 7) {
        int ao = i / 392, r = i % 392, ai = r / 7, k = r % 7;
        g_wemb_t[(ai * 7 + k) * 56 + ao] = w_emb[i];
    }
    if (i < 128 * 128 * 7) {
        int eo = i / 896, r = i % 896, ei = r / 7, k = r % 7;
        g_watlas_t[(ei * 7 + k) * 128 + eo] = w_atlas[i];
    }
    if (i < 128 * 128) {
        int o = i / 128, e = i % 128;
        g_wk_t[e * 128 + o] = w_k[i];
    }
}

// ---------------- K1: conv1 over E + SiLU -> h1T -----------------------------
// 1 batch per 128-thread CTA. Thread: e-pair (t&63), a_out half (t>>6).
__global__ void __launch_bounds__(128, 5)
conv1_kernel(const float* __restrict__ x, const float* __restrict__ b_emb) {
    __shared__ float xs[56 * XS_W];
    int t = threadIdx.x;
    int b = blockIdx.x;

    const float* xb = x + (size_t)b * 56 * 128;
    for (int i = t; i < 56 * 128; i += 128) {
        int a = i >> 7, e = i & 127;
        xs[a * XS_W + 3 + e] = xb[i];
    }
    if (t < 56) {
        float* row = xs + t * XS_W;
        row[0] = 0.f; row[1] = 0.f; row[2] = 0.f;
        row[131] = 0.f; row[132] = 0.f; row[133] = 0.f; row[134] = 0.f; row[135] = 0.f;
    }
    __syncthreads();

    int ep = t & 63, ah = t >> 6;
    int e0 = 2 * ep, aoff = 28 * ah;

    unsigned long long acc0[14], acc1[14];
#pragma unroll
    for (int j = 0; j < 14; j++) { acc0[j] = 0ULL; acc1[j] = 0ULL; }

    for (int ai = 0; ai < 56; ai++) {
        const float* xr = xs + ai * XS_W + e0;
        float xv[8];
#pragma unroll
        for (int j = 0; j < 8; j++) xv[j] = xr[j];
#pragma unroll
        for (int k = 0; k < 7; k++) {
            unsigned long long xb0 = bc2(xv[k]);
            unsigned long long xb1 = bc2(xv[k + 1]);
            const ulonglong2* wr = reinterpret_cast<const ulonglong2*>(
                g_wemb_t + (ai * 7 + k) * 56 + aoff);
#pragma unroll
            for (int p = 0; p < 7; p++) {
                ulonglong2 w = wr[p];
                fma2(acc0[2 * p],     w.x, xb0);
                fma2(acc0[2 * p + 1], w.y, xb0);
                fma2(acc1[2 * p],     w.x, xb1);
                fma2(acc1[2 * p + 1], w.y, xb1);
            }
        }
    }

#pragma unroll
    for (int v = 0; v < 2; v++) {
        float* dst = g_h1 + ((size_t)b * 128 + e0 + v) * 64;
        if (ah == 0) { dst[0] = 0.f; dst[1] = 0.f; dst[2] = 0.f; }
        else { dst[59] = 0.f; dst[60] = 0.f; dst[61] = 0.f; dst[62] = 0.f; dst[63] = 0.f; }
        const unsigned long long* av = v ? acc1 : acc0;
        int base = 3 + aoff;
#pragma unroll
        for (int j = 0; j < 14; j++) {
            float2 f = unpk(av[j]);
            dst[base + 2 * j]     = silu_f(f.x + b_emb[aoff + 2 * j]);
            dst[base + 2 * j + 1] = silu_f(f.y + b_emb[aoff + 2 * j + 1]);
        }
    }
}

// ---------------- K2: conv2 over A + SiLU + mean -> q ------------------------
// 1 batch per 224-thread CTA: tx = a-quad (14), g = eo-octet (16).
__global__ void __launch_bounds__(224, 3)
conv2_kernel(const float* __restrict__ b_atlas) {
    __shared__ __align__(16) float h1s[128 * 64];
    __shared__ float qsum[128];
    int tid = threadIdx.x;
    int b = blockIdx.x;

    const float4* src = reinterpret_cast<const float4*>(g_h1 + (size_t)b * 8192);
    float4* dst4 = reinterpret_cast<float4*>(h1s);
    for (int i = tid; i < 2048; i += 224) dst4[i] = src[i];
    if (tid < 128) qsum[tid] = 0.f;
    __syncthreads();

    int tx = tid % 14, g = tid / 14;
    int a0 = 4 * tx, eo0 = 8 * g;

    unsigned long long acc[4][4];
#pragma unroll
    for (int a = 0; a < 4; a++)
#pragma unroll
        for (int p = 0; p < 4; p++) acc[a][p] = 0ULL;

    for (int ei = 0; ei < 128; ei++) {
        const float* hr = h1s + ei * 64 + a0;
        float xv[10];
#pragma unroll
        for (int j = 0; j < 10; j++) xv[j] = hr[j];
#pragma unroll
        for (int k = 0; k < 7; k++) {
            const ulonglong2* wr = reinterpret_cast<const ulonglong2*>(
                g_watlas_t + (ei * 7 + k) * 128 + eo0);
            ulonglong2 wA = wr[0];
            ulonglong2 wB = wr[1];
#pragma unroll
            for (int a = 0; a < 4; a++) {
                unsigned long long xb = bc2(xv[k + a]);
                fma2(acc[a][0], wA.x, xb);
                fma2(acc[a][1], wA.y, xb);
                fma2(acc[a][2], wB.x, xb);
                fma2(acc[a][3], wB.y, xb);
            }
        }
    }

    float s[8];
#pragma unroll
    for (int j = 0; j < 8; j++) s[j] = 0.f;
#pragma unroll
    for (int a = 0; a < 4; a++)
#pragma unroll
        for (int p = 0; p < 4; p++) {
            float2 f = unpk(acc[a][p]);
            s[2 * p]     += silu_f(f.x + b_atlas[eo0 + 2 * p]);
            s[2 * p + 1] += silu_f(f.y + b_atlas[eo0 + 2 * p + 1]);
        }
#pragma unroll
    for (int j = 0; j < 8; j++) atomicAdd(&qsum[eo0 + j], s[j]);
    __syncthreads();
    if (tid < 128) g_q[b * 128 + tid] = qsum[tid] * (1.0f / 56.0f);
}

// ---------------- K3: k-proj + LN + attention + diff-softmax -----------------
// 1 batch per 128-thread CTA.
__global__ void __launch_bounds__(128, 4)
attn_kernel(const float* __restrict__ x,
            const float* __restrict__ qn_w, const float* __restrict__ qn_b,
            const float* __restrict__ kn_w, const float* __restrict__ kn_b,
            const float* __restrict__ lq1, const float* __restrict__ lk1,
            const float* __restrict__ lq2, const float* __restrict__ lk2,
            float* __restrict__ out) {
    extern __shared__ __align__(16) float sm[];
    int t = threadIdx.x;
    int b = blockIdx.x;

    float* xsT = sm;            // [e][l] l contiguous (128*56)
    float* ks  = sm + 7168;     // [l][o] (56*128)
    float* qv  = sm + 14336;    // 128
    float* sc  = sm + 14464;    // [h2][l] 8*56
    float* dd  = sm + 14912;    // [hp][l] 4*56
    float* lam = sm + 15136;

    const float* xb = x + (size_t)b * 7168;
    for (int i = t; i < 7168; i += 128) {
        int l = i >> 7, e = i & 127;
        xsT[e * 56 + l] = xb[i];
    }
    qv[t] = g_q[b * 128 + t];
    if (t == 0) {
        float s1 = 0.f, s2 = 0.f;
#pragma unroll
        for (int d = 0; d < 16; d++) { s1 += lq1[d] * lk1[d]; s2 += lq2[d] * lk2[d]; }
        lam[0] = __expf(s1) - __expf(s2) + 0.7f;
    }
    __syncthreads();

    // k projection: thread t owns output column o=t; f32x2 lanes = l pairs
    unsigned long long acc[28];
#pragma unroll
    for (int p = 0; p < 28; p++) acc[p] = 0ULL;
    for (int e = 0; e < 128; e++) {
        unsigned long long wb = bc2(g_wk_t[e * 128 + t]);
        const ulonglong2* xr = reinterpret_cast<const ulonglong2*>(xsT + e * 56);
#pragma unroll
        for (int p = 0; p < 14; p++) {
            ulonglong2 xq = xr[p];
            fma2(acc[2 * p],     xq.x, wb);
            fma2(acc[2 * p + 1], xq.y, wb);
        }
    }
#pragma unroll
    for (int j = 0; j < 28; j++) {
        float2 f = unpk(acc[j]);
        ks[(2 * j) * 128 + t]     = f.x;
        ks[(2 * j + 1) * 128 + t] = f.y;
    }
    __syncthreads();

    // LayerNorm k (448 head-rows) and q (8 head-rows)
    for (int gI = t; gI < 448; gI += 128) {
        int l = gI >> 3, h = gI & 7;
        float* kp = ks + l * 128 + h * 16;
        float m = 0.f;
#pragma unroll
        for (int d = 0; d < 16; d++) m += kp[d];
        m *= (1.0f / 16.0f);
        float var = 0.f;
#pragma unroll
        for (int d = 0; d < 16; d++) { float dv = kp[d] - m; var += dv * dv; }
        var *= (1.0f / 16.0f);
        float rs = rsqrtf(var + 1e-5f);
#pragma unroll
        for (int d = 0; d < 16; d++)
            kp[d] = (kp[d] - m) * rs * kn_w[d] + kn_b[d];
    }
    if (t < 8) {
        float* qp = qv + t * 16;
        float m = 0.f;
#pragma unroll
        for (int d = 0; d < 16; d++) m += qp[d];
        m *= (1.0f / 16.0f);
        float var = 0.f;
#pragma unroll
        for (int d = 0; d < 16; d++) { float dv = qp[d] - m; var += dv * dv; }
        var *= (1.0f / 16.0f);
        float rs = rsqrtf(var + 1e-5f);
#pragma unroll
        for (int d = 0; d < 16; d++)
            qp[d] = ((qp[d] - m) * rs * qn_w[d] + qn_b[d]) * 0.25f; // * HD^-0.5
    }
    __syncthreads();

    // attention scores
    for (int gI = t; gI < 448; gI += 128) {
        int l = gI >> 3, h = gI & 7;
        const float* kp = ks + l * 128 + h * 16;
        const float* qp = qv + h * 16;
        float s = 0.f;
#pragma unroll
        for (int d = 0; d < 16; d++) s += qp[d] * kp[d];
        sc[h * 56 + l] = s;
    }
    __syncthreads();

    // softmax per head
    if (t < 8) {
        float* r = sc + t * 56;
        float mx = -1e30f;
        for (int l = 0; l < 56; l++) mx = fmaxf(mx, r[l]);
        float sum = 0.f;
        for (int l = 0; l < 56; l++) { float e = __expf(r[l] - mx); r[l] = e; sum += e; }
        float inv = 1.0f / sum;
        for (int l = 0; l < 56; l++) r[l] *= inv;
    }
    __syncthreads();

    // diff + softmax per head pair
    if (t < 4) {
        float lamv = lam[0];
        const float* p0 = sc + (2 * t) * 56;
        const float* p1 = sc + (2 * t + 1) * 56;
        float* dr = dd + t * 56;
        float mx = -1e30f;
        for (int l = 0; l < 56; l++) {
            float d = p0[l] - lamv * p1[l];
            dr[l] = d;
            mx = fmaxf(mx, d);
        }
        float sum = 0.f;
        for (int l = 0; l < 56; l++) { float e = __expf(dr[l] - mx); dr[l] = e; sum += e; }
        float inv = 1.0f / sum;
        for (int l = 0; l < 56; l++) dr[l] *= inv;
    }
    __syncthreads();

    if (t < 56) {
        out[(size_t)b * 56 + t] =
            0.25f * (dd[t] + dd[56 + t] + dd[112 + t] + dd[168 + t]);
    }
}

// ---------------- launch -----------------------------------------------------
extern "C" void kernel_launch(void* const* d_in, const int* in_sizes, int n_in,
                              void* d_out, int out_size) {
    const float* x       = (const float*)d_in[0];
    const float* w_emb   = (const float*)d_in[1];
    const float* b_emb   = (const float*)d_in[2];
    const float* w_atlas = (const float*)d_in[3];
    const float* b_atlas = (const float*)d_in[4];
    const float* w_k     = (const float*)d_in[5];
    const float* qn_w    = (const float*)d_in[6];
    const float* qn_b    = (const float*)d_in[7];
    const float* kn_w    = (const float*)d_in[8];
    const float* kn_b    = (const float*)d_in[9];
    const float* lq1     = (const float*)d_in[10];
    const float* lk1     = (const float*)d_in[11];
    const float* lq2     = (const float*)d_in[12];
    const float* lk2     = (const float*)d_in[13];
    float* out = (float*)d_out;

    const int SMEM3 = 15140 * (int)sizeof(float);  // 60,560 B dynamic
    static int s_attr_done = 0;
    if (!s_attr_done) {
        cudaFuncSetAttribute((const void*)attn_kernel,
                             cudaFuncAttributeMaxDynamicSharedMemorySize, SMEM3);
        s_attr_done = 1;
    }

    repack_kernel<<<448, 256>>>(w_emb, w_atlas, w_k);
    conv1_kernel<<<NB, 128>>>(x, b_emb);
    conv2_kernel<<<NB, 224>>>(b_atlas);
    attn_kernel<<<NB, 128, SMEM3>>>(x, qn_w, qn_b, kn_w, kn_b,
                                    lq1, lk1, lq2, lk2, out);
    (void)in_sizes; (void)n_in; (void)out_size;
}